// round 3
// baseline (speedup 1.0000x reference)
#include <cuda_runtime.h>
#include <cstdint>

#define BATCH   1024
#define SENS    128
#define NSTATE  256
#define MOUT    32
#define NUNFOLD 6
#define BB      8          // batch rows per block
#define HB      4          // batch rows per thread (two 256-thread halves)
#define EPSV    1e-8f
#define CAP_R   176        // max active pre-neurons per column (mean 128, +6 sigma)
#define CAP_S   104        // sensory (mean 64, +7 sigma)

// Compacted params, tanh form: sigmoid(s*(v-m)) = 0.5 + 0.5*tanh(0.5*s*(v-m))
//   x = 0.5*sigma  (low 8 mantissa bits replaced by pre-neuron index)
//   y = -0.5*sigma*mu
//   z = 0.5*w*mask
//   w = 0.5*w*erev*mask
__device__ float4 g_cparams[CAP_R * NSTATE];
__device__ float4 g_csparams[CAP_S * NSTATE];
__device__ int    g_ccnt[NSTATE];
__device__ int    g_cscnt[NSTATE];
__device__ float2 g_col[NSTATE];    // (sum z, sum w) over active recurrent entries
__device__ float2 g_scol[NSTATE];   // sensory

__device__ __forceinline__ float ftanh(float x) {
    float y; asm("tanh.approx.f32 %0, %1;" : "=f"(y) : "f"(x)); return y;
}
__device__ __forceinline__ float frcp(float x) {
    float y; asm("rcp.approx.ftz.f32 %0, %1;" : "=f"(y) : "f"(x)); return y;
}

// Deterministic per-column compaction. block 0 = recurrent, block 1 = sensory.
// Thread j scans its column in ascending i; reads are warp-coalesced (lane = j).
__global__ void compact_kernel(const float* __restrict__ sigma, const float* __restrict__ mu,
                               const float* __restrict__ w,     const float* __restrict__ erev,
                               const float* __restrict__ mask,
                               const float* __restrict__ ssigma, const float* __restrict__ smu,
                               const float* __restrict__ sw,     const float* __restrict__ serev,
                               const float* __restrict__ smask)
{
    const int j = threadIdx.x;
    if (blockIdx.x == 0) {
        int c = 0; float sz = 0.0f, sn = 0.0f;
        for (int i = 0; i < NSTATE; i++) {
            const int off = i * NSTATE + j;
            float m = mask[off];
            if (m != 0.0f) {
                float sg = 0.5f * sigma[off];
                float y  = -sg * mu[off];
                float z  = 0.5f * w[off] * m;
                float wn = 0.5f * w[off] * erev[off] * m;
                uint32_t xb = (__float_as_uint(sg) & 0xFFFFFF00u) | (uint32_t)i;
                sz += z; sn += wn;
                if (c < CAP_R) g_cparams[c * NSTATE + j] =
                    make_float4(__uint_as_float(xb), y, z, wn);
                c++;
            }
        }
        int cnt = (c < CAP_R) ? c : CAP_R;
        g_ccnt[j] = cnt;
        for (int p = cnt; p < CAP_R; p++)
            g_cparams[p * NSTATE + j] = make_float4(1.0f, 0.0f, 0.0f, 0.0f);
        g_col[j] = make_float2(sz, sn);
    } else {
        int c = 0; float sz = 0.0f, sn = 0.0f;
        for (int s = 0; s < SENS; s++) {
            const int off = s * NSTATE + j;
            float m = smask[off];
            if (m != 0.0f) {
                float sg = 0.5f * ssigma[off];
                float y  = -sg * smu[off];
                float z  = 0.5f * sw[off] * m;
                float wn = 0.5f * sw[off] * serev[off] * m;
                uint32_t xb = (__float_as_uint(sg) & 0xFFFFFF00u) | (uint32_t)s;
                sz += z; sn += wn;
                if (c < CAP_S) g_csparams[c * NSTATE + j] =
                    make_float4(__uint_as_float(xb), y, z, wn);
                c++;
            }
        }
        int cnt = (c < CAP_S) ? c : CAP_S;
        g_cscnt[j] = cnt;
        for (int p = cnt; p < CAP_S; p++)
            g_csparams[p * NSTATE + j] = make_float4(1.0f, 0.0f, 0.0f, 0.0f);
        g_scol[j] = make_float2(sz, sn);
    }
}

__global__ __launch_bounds__(512, 1)
void ltc_kernel(const float* __restrict__ inputs, const float* __restrict__ states,
                const float* __restrict__ gleak,  const float* __restrict__ vleak,
                const float* __restrict__ cm,
                const float* __restrict__ input_w, const float* __restrict__ input_b,
                const float* __restrict__ output_w, const float* __restrict__ output_b,
                float* __restrict__ out)
{
    // Transposed shared: batch index contiguous so gathers are single LDS.128
    __shared__ float sxT[SENS][BB];      // mapped sensory inputs
    __shared__ float svT[NSTATE][BB];    // current state

    const int tid = threadIdx.x;
    const int j   = tid & (NSTATE - 1);  // output neuron
    const int h   = tid >> 8;            // batch half
    const int bb0 = h * HB;
    const int b0  = blockIdx.x * BB;

    // Load inputs (coalesced read, transposed store)
    for (int t = tid; t < BB * SENS; t += 512) {
        int bb = t >> 7, s = t & (SENS - 1);
        sxT[s][bb] = inputs[(b0 + bb) * SENS + s] * input_w[s] + input_b[s];
    }
    for (int t = tid; t < BB * NSTATE; t += 512) {
        int bb = t >> 8, jj = t & (NSTATE - 1);
        svT[jj][bb] = states[(b0 + bb) * NSTATE + jj];
    }
    __syncthreads();

    // ---- Sensory reduction (once) ----
    float sden[HB], snum[HB];
    #pragma unroll
    for (int k = 0; k < HB; k++) { sden[k] = 0.0f; snum[k] = 0.0f; }

    const int smax = __reduce_max_sync(0xFFFFFFFFu, g_cscnt[j]);
    #pragma unroll 2
    for (int c = 0; c < smax; c++) {
        float4 p = g_csparams[c * NSTATE + j];
        int idx = (int)(__float_as_uint(p.x) & 0xFFu);
        float4 xv = *reinterpret_cast<const float4*>(&sxT[idx][bb0]);
        float t0 = ftanh(fmaf(p.x, xv.x, p.y));
        float t1 = ftanh(fmaf(p.x, xv.y, p.y));
        float t2 = ftanh(fmaf(p.x, xv.z, p.y));
        float t3 = ftanh(fmaf(p.x, xv.w, p.y));
        sden[0] = fmaf(p.z, t0, sden[0]);  snum[0] = fmaf(p.w, t0, snum[0]);
        sden[1] = fmaf(p.z, t1, sden[1]);  snum[1] = fmaf(p.w, t1, snum[1]);
        sden[2] = fmaf(p.z, t2, sden[2]);  snum[2] = fmaf(p.w, t2, snum[2]);
        sden[3] = fmaf(p.z, t3, sden[3]);  snum[3] = fmaf(p.w, t3, snum[3]);
    }
    {
        float2 sc = g_scol[j];
        #pragma unroll
        for (int k = 0; k < HB; k++) { sden[k] += sc.x; snum[k] += sc.y; }
    }

    // Per-neuron constants
    const float gl   = gleak[j];
    const float gv   = gl * vleak[j];
    const float cmt  = cm[j] * (float)NUNFOLD;    // cm / (DT/UNFOLDS), DT=1
    const float2 col = g_col[j];
    const int   rmax = __reduce_max_sync(0xFFFFFFFFu, g_ccnt[j]);

    // ---- Unfold loop ----
    for (int u = 0; u < NUNFOLD; u++) {
        float den[HB], num[HB];
        #pragma unroll
        for (int k = 0; k < HB; k++) {
            den[k] = sden[k] + col.x;
            num[k] = snum[k] + col.y;
        }

        #pragma unroll 2
        for (int c = 0; c < rmax; c++) {
            float4 p = g_cparams[c * NSTATE + j];
            int idx = (int)(__float_as_uint(p.x) & 0xFFu);
            float4 vv = *reinterpret_cast<const float4*>(&svT[idx][bb0]);
            float t0 = ftanh(fmaf(p.x, vv.x, p.y));
            float t1 = ftanh(fmaf(p.x, vv.y, p.y));
            float t2 = ftanh(fmaf(p.x, vv.z, p.y));
            float t3 = ftanh(fmaf(p.x, vv.w, p.y));
            den[0] = fmaf(p.z, t0, den[0]);  num[0] = fmaf(p.w, t0, num[0]);
            den[1] = fmaf(p.z, t1, den[1]);  num[1] = fmaf(p.w, t1, num[1]);
            den[2] = fmaf(p.z, t2, den[2]);  num[2] = fmaf(p.w, t2, num[2]);
            den[3] = fmaf(p.z, t3, den[3]);  num[3] = fmaf(p.w, t3, num[3]);
        }

        __syncthreads();   // all gathers of svT done
        {
            float4 vold = *reinterpret_cast<const float4*>(&svT[j][bb0]);
            float4 vnew;
            vnew.x = fmaf(cmt, vold.x, gv * num[0]) * frcp(cmt + gl + den[0] + EPSV);
            vnew.y = fmaf(cmt, vold.y, gv * num[1]) * frcp(cmt + gl + den[1] + EPSV);
            vnew.z = fmaf(cmt, vold.z, gv * num[2]) * frcp(cmt + gl + den[2] + EPSV);
            vnew.w = fmaf(cmt, vold.w, gv * num[3]) * frcp(cmt + gl + den[3] + EPSV);
            *reinterpret_cast<float4*>(&svT[j][bb0]) = vnew;
        }
        __syncthreads();   // new state visible
    }

    // ---- Write outputs: [outputs (B,M)] then [v_pre (B,N)] ----
    const float ow = (j < MOUT) ? output_w[j] : 0.0f;
    const float ob = (j < MOUT) ? output_b[j] : 0.0f;
    #pragma unroll
    for (int k = 0; k < HB; k++) {
        float v = svT[j][bb0 + k];
        out[BATCH * MOUT + (b0 + bb0 + k) * NSTATE + j] = v;
        if (j < MOUT)
            out[(b0 + bb0 + k) * MOUT + j] = fmaf(v, ow, ob);
    }
}

extern "C" void kernel_launch(void* const* d_in, const int* in_sizes, int n_in,
                              void* d_out, int out_size)
{
    const float* inputs   = (const float*)d_in[0];
    const float* states   = (const float*)d_in[1];
    const float* gleak    = (const float*)d_in[2];
    const float* vleak    = (const float*)d_in[3];
    const float* cm       = (const float*)d_in[4];
    const float* sigma    = (const float*)d_in[5];
    const float* mu       = (const float*)d_in[6];
    const float* w        = (const float*)d_in[7];
    const float* erev     = (const float*)d_in[8];
    const float* ssigma   = (const float*)d_in[9];
    const float* smu      = (const float*)d_in[10];
    const float* sw       = (const float*)d_in[11];
    const float* serev    = (const float*)d_in[12];
    const float* input_w  = (const float*)d_in[13];
    const float* input_b  = (const float*)d_in[14];
    const float* output_w = (const float*)d_in[15];
    const float* output_b = (const float*)d_in[16];
    const float* mask     = (const float*)d_in[17];
    const float* smask    = (const float*)d_in[18];
    float* out = (float*)d_out;

    compact_kernel<<<2, NSTATE>>>(
        sigma, mu, w, erev, mask, ssigma, smu, sw, serev, smask);

    ltc_kernel<<<BATCH / BB, 512>>>(
        inputs, states, gleak, vleak, cm,
        input_w, input_b, output_w, output_b, out);
}

// round 5
// speedup vs baseline: 1.3782x; 1.3782x over previous
#include <cuda_runtime.h>
#include <cstdint>

#define BATCH   1024
#define SENS    128
#define NSTATE  256
#define MOUT    32
#define NUNFOLD 6
#define BB      8          // batch rows per block
#define HB      4          // batch rows per thread (two 256-thread halves)
#define EPSV    1e-8f
#define CAP_R   176        // max active pre-neurons per column
#define CAP_S   104        // sensory cap

// Compacted params (indexed by SLOT, i.e. sorted column order), tanh form:
//   sigmoid(s*(v-m)) = 0.5 + 0.5*tanh(0.5*s*(v-m))
//   x = 0.5*sigma (low 8 mantissa bits carry pre-neuron index)
//   y = -0.5*sigma*mu,  z = 0.5*w*mask,  w = 0.5*w*erev*mask
__device__ float4 g_cparams[CAP_R * NSTATE];
__device__ float4 g_csparams[CAP_S * NSTATE];
__device__ int    g_ccnt[NSTATE];     // per-slot recurrent count
__device__ int    g_cscnt[NSTATE];    // per-slot sensory count
__device__ float2 g_col[NSTATE];      // per-slot (sum z, sum w) recurrent
__device__ float2 g_scol[NSTATE];     // per-slot sensory
__device__ int    g_rcntJ[NSTATE];    // per-column counts (pre-sort)
__device__ int    g_scntJ[NSTATE];
__device__ int    g_perm[NSTATE];     // slot -> column

__device__ __forceinline__ float ftanh(float x) {
    float y; asm("tanh.approx.f32 %0, %1;" : "=f"(y) : "f"(x)); return y;
}
__device__ __forceinline__ float frcp(float x) {
    float y; asm("rcp.approx.ftz.f32 %0, %1;" : "=f"(y) : "f"(x)); return y;
}

// ---- Pass 1: per-column active counts (one warp per column) ----
__global__ void count_kernel(const float* __restrict__ mask,
                             const float* __restrict__ smask)
{
    int warp = (blockIdx.x * blockDim.x + threadIdx.x) >> 5;
    int lane = threadIdx.x & 31;
    if (warp >= NSTATE) return;
    int j = warp;
    int rc = 0, sc = 0;
    for (int i = lane; i < NSTATE; i += 32) rc += (mask [i * NSTATE + j] != 0.0f);
    for (int s = lane; s < SENS;   s += 32) sc += (smask[s * NSTATE + j] != 0.0f);
    #pragma unroll
    for (int o = 16; o; o >>= 1) {
        rc += __shfl_xor_sync(0xFFFFFFFFu, rc, o);
        sc += __shfl_xor_sync(0xFFFFFFFFu, sc, o);
    }
    if (lane == 0) { g_rcntJ[j] = rc; g_scntJ[j] = sc; }
}

// ---- Pass 2: deterministic rank by weight, build slot->column perm ----
__global__ void rank_kernel()
{
    __shared__ int key[NSTATE];
    int j = threadIdx.x;
    key[j] = NUNFOLD * g_rcntJ[j] + g_scntJ[j];
    __syncthreads();
    int kj = key[j];
    int r = 0;
    for (int k = 0; k < NSTATE; k++) {
        int kk = key[k];
        r += (kk < kj) || (kk == kj && k < j);
    }
    g_perm[r] = j;
}

// ---- Pass 3: order-preserving warp compaction into slot-major storage ----
// warps [0, NSTATE)        : recurrent column for slot = warp
// warps [NSTATE, 2*NSTATE) : sensory column for slot = warp - NSTATE
__global__ void compact_kernel(const float* __restrict__ sigma, const float* __restrict__ mu,
                               const float* __restrict__ w,     const float* __restrict__ erev,
                               const float* __restrict__ mask,
                               const float* __restrict__ ssigma, const float* __restrict__ smu,
                               const float* __restrict__ sw,     const float* __restrict__ serev,
                               const float* __restrict__ smask)
{
    int warp = (blockIdx.x * blockDim.x + threadIdx.x) >> 5;
    int lane = threadIdx.x & 31;
    if (warp >= 2 * NSTATE) return;

    if (warp < NSTATE) {
        const int slot = warp;
        const int j    = g_perm[slot];
        int c = 0; float sz = 0.0f, sn = 0.0f;
        for (int base = 0; base < NSTATE; base += 32) {
            int i   = base + lane;
            int off = i * NSTATE + j;
            float m = mask[off];
            bool act = (m != 0.0f);
            unsigned bal = __ballot_sync(0xFFFFFFFFu, act);
            int pos = c + __popc(bal & ((1u << lane) - 1u));
            if (act) {
                float sg = 0.5f * sigma[off];
                float y  = -sg * mu[off];
                float z  = 0.5f * w[off] * m;
                float wn = 0.5f * w[off] * erev[off] * m;
                uint32_t xb = (__float_as_uint(sg) & 0xFFFFFF00u) | (uint32_t)i;
                sz += z; sn += wn;
                if (pos < CAP_R)
                    g_cparams[pos * NSTATE + slot] = make_float4(__uint_as_float(xb), y, z, wn);
            }
            c += __popc(bal);
        }
        #pragma unroll
        for (int o = 16; o; o >>= 1) {
            sz += __shfl_xor_sync(0xFFFFFFFFu, sz, o);
            sn += __shfl_xor_sync(0xFFFFFFFFu, sn, o);
        }
        int cnt = (c < CAP_R) ? c : CAP_R;
        if (lane == 0) { g_ccnt[slot] = cnt; g_col[slot] = make_float2(sz, sn); }
        for (int p = cnt + lane; p < CAP_R; p += 32)
            g_cparams[p * NSTATE + slot] = make_float4(1.0f, 0.0f, 0.0f, 0.0f);
    } else {
        const int sslot = warp - NSTATE;
        const int j     = g_perm[sslot];
        int c = 0; float sz = 0.0f, sn = 0.0f;
        for (int base = 0; base < SENS; base += 32) {
            int s   = base + lane;
            int off = s * NSTATE + j;
            float m = smask[off];
            bool act = (m != 0.0f);
            unsigned bal = __ballot_sync(0xFFFFFFFFu, act);
            int pos = c + __popc(bal & ((1u << lane) - 1u));
            if (act) {
                float sg = 0.5f * ssigma[off];
                float y  = -sg * smu[off];
                float z  = 0.5f * sw[off] * m;
                float wn = 0.5f * sw[off] * serev[off] * m;
                uint32_t xb = (__float_as_uint(sg) & 0xFFFFFF00u) | (uint32_t)s;
                sz += z; sn += wn;
                if (pos < CAP_S)
                    g_csparams[pos * NSTATE + sslot] = make_float4(__uint_as_float(xb), y, z, wn);
            }
            c += __popc(bal);
        }
        #pragma unroll
        for (int o = 16; o; o >>= 1) {
            sz += __shfl_xor_sync(0xFFFFFFFFu, sz, o);
            sn += __shfl_xor_sync(0xFFFFFFFFu, sn, o);
        }
        int cnt = (c < CAP_S) ? c : CAP_S;
        if (lane == 0) { g_cscnt[sslot] = cnt; g_scol[sslot] = make_float2(sz, sn); }
        for (int p = cnt + lane; p < CAP_S; p += 32)
            g_csparams[p * NSTATE + sslot] = make_float4(1.0f, 0.0f, 0.0f, 0.0f);
    }
}

// ---- Main kernel ----
__global__ __launch_bounds__(512, 1)
void ltc_kernel(const float* __restrict__ inputs, const float* __restrict__ states,
                const float* __restrict__ gleak,  const float* __restrict__ vleak,
                const float* __restrict__ cm,
                const float* __restrict__ input_w, const float* __restrict__ input_b,
                const float* __restrict__ output_w, const float* __restrict__ output_b,
                float* __restrict__ out)
{
    // 16B row stride per half -> gather start banks spread over 8 groups (conflict-light)
    __shared__ float4 sx4[2][SENS];      // mapped sensory inputs
    __shared__ float4 sv4[2][NSTATE];    // current state

    const int tid = threadIdx.x;
    const int t   = tid & (NSTATE - 1);  // slot
    const int h   = tid >> 8;            // batch half
    const int b0  = blockIdx.x * BB;
    const int j   = g_perm[t];           // this thread's column

    // Load inputs (coalesced read -> transposed scalar store)
    float* sxf = (float*)sx4;
    float* svf = (float*)sv4;
    for (int q = tid; q < BB * SENS; q += 512) {
        int bb = q >> 7, s = q & (SENS - 1);
        sxf[((bb >> 2) * SENS + s) * 4 + (bb & 3)] =
            inputs[(b0 + bb) * SENS + s] * input_w[s] + input_b[s];
    }
    for (int q = tid; q < BB * NSTATE; q += 512) {
        int bb = q >> 8, jj = q & (NSTATE - 1);
        svf[((bb >> 2) * NSTATE + jj) * 4 + (bb & 3)] =
            states[(b0 + bb) * NSTATE + jj];
    }
    __syncthreads();

    // ---- Sensory reduction (once) ----
    float sden[HB], snum[HB];
    #pragma unroll
    for (int k = 0; k < HB; k++) { sden[k] = 0.0f; snum[k] = 0.0f; }

    const int smax = __reduce_max_sync(0xFFFFFFFFu, g_cscnt[t]);
    #pragma unroll 2
    for (int c = 0; c < smax; c++) {
        float4 p = g_csparams[c * NSTATE + t];
        int idx = (int)(__float_as_uint(p.x) & 0xFFu);
        float4 xv = sx4[h][idx];
        float t0 = ftanh(fmaf(p.x, xv.x, p.y));
        float t1 = ftanh(fmaf(p.x, xv.y, p.y));
        float t2 = ftanh(fmaf(p.x, xv.z, p.y));
        float t3 = ftanh(fmaf(p.x, xv.w, p.y));
        sden[0] = fmaf(p.z, t0, sden[0]);  snum[0] = fmaf(p.w, t0, snum[0]);
        sden[1] = fmaf(p.z, t1, sden[1]);  snum[1] = fmaf(p.w, t1, snum[1]);
        sden[2] = fmaf(p.z, t2, sden[2]);  snum[2] = fmaf(p.w, t2, snum[2]);
        sden[3] = fmaf(p.z, t3, sden[3]);  snum[3] = fmaf(p.w, t3, snum[3]);
    }
    {
        float2 sc = g_scol[t];
        #pragma unroll
        for (int k = 0; k < HB; k++) { sden[k] += sc.x; snum[k] += sc.y; }
    }

    // Per-neuron constants (column-indexed)
    const float gl   = gleak[j];
    const float gv   = gl * vleak[j];
    const float cmt  = cm[j] * (float)NUNFOLD;    // cm / (DT/UNFOLDS), DT=1
    const float2 col = g_col[t];
    const int   rmax = __reduce_max_sync(0xFFFFFFFFu, g_ccnt[t]);

    // ---- Unfold loop ----
    for (int u = 0; u < NUNFOLD; u++) {
        float den[HB], num[HB];
        #pragma unroll
        for (int k = 0; k < HB; k++) {
            den[k] = sden[k] + col.x;
            num[k] = snum[k] + col.y;
        }

        #pragma unroll 2
        for (int c = 0; c < rmax; c++) {
            float4 p = g_cparams[c * NSTATE + t];
            int idx = (int)(__float_as_uint(p.x) & 0xFFu);
            float4 vv = sv4[h][idx];
            float t0 = ftanh(fmaf(p.x, vv.x, p.y));
            float t1 = ftanh(fmaf(p.x, vv.y, p.y));
            float t2 = ftanh(fmaf(p.x, vv.z, p.y));
            float t3 = ftanh(fmaf(p.x, vv.w, p.y));
            den[0] = fmaf(p.z, t0, den[0]);  num[0] = fmaf(p.w, t0, num[0]);
            den[1] = fmaf(p.z, t1, den[1]);  num[1] = fmaf(p.w, t1, num[1]);
            den[2] = fmaf(p.z, t2, den[2]);  num[2] = fmaf(p.w, t2, num[2]);
            den[3] = fmaf(p.z, t3, den[3]);  num[3] = fmaf(p.w, t3, num[3]);
        }

        __syncthreads();   // all gathers done
        {
            float4 vold = sv4[h][j];
            float4 vnew;
            vnew.x = fmaf(cmt, vold.x, gv * num[0]) * frcp(cmt + gl + den[0] + EPSV);
            vnew.y = fmaf(cmt, vold.y, gv * num[1]) * frcp(cmt + gl + den[1] + EPSV);
            vnew.z = fmaf(cmt, vold.z, gv * num[2]) * frcp(cmt + gl + den[2] + EPSV);
            vnew.w = fmaf(cmt, vold.w, gv * num[3]) * frcp(cmt + gl + den[3] + EPSV);
            sv4[h][j] = vnew;
        }
        __syncthreads();   // new state visible
    }

    // ---- Write outputs: [outputs (B,M)] then [v_pre (B,N)] ----
    const float ow = (j < MOUT) ? output_w[j] : 0.0f;
    const float ob = (j < MOUT) ? output_b[j] : 0.0f;
    float4 vfin = sv4[h][j];
    float vk[HB] = {vfin.x, vfin.y, vfin.z, vfin.w};
    #pragma unroll
    for (int k = 0; k < HB; k++) {
        int b = b0 + h * HB + k;
        out[BATCH * MOUT + b * NSTATE + j] = vk[k];
        if (j < MOUT)
            out[b * MOUT + j] = fmaf(vk[k], ow, ob);
    }
}

extern "C" void kernel_launch(void* const* d_in, const int* in_sizes, int n_in,
                              void* d_out, int out_size)
{
    const float* inputs   = (const float*)d_in[0];
    const float* states   = (const float*)d_in[1];
    const float* gleak    = (const float*)d_in[2];
    const float* vleak    = (const float*)d_in[3];
    const float* cm       = (const float*)d_in[4];
    const float* sigma    = (const float*)d_in[5];
    const float* mu       = (const float*)d_in[6];
    const float* w        = (const float*)d_in[7];
    const float* erev     = (const float*)d_in[8];
    const float* ssigma   = (const float*)d_in[9];
    const float* smu      = (const float*)d_in[10];
    const float* sw       = (const float*)d_in[11];
    const float* serev    = (const float*)d_in[12];
    const float* input_w  = (const float*)d_in[13];
    const float* input_b  = (const float*)d_in[14];
    const float* output_w = (const float*)d_in[15];
    const float* output_b = (const float*)d_in[16];
    const float* mask     = (const float*)d_in[17];
    const float* smask    = (const float*)d_in[18];
    float* out = (float*)d_out;

    count_kernel<<<32, 256>>>(mask, smask);                 // 256 warps
    rank_kernel<<<1, 256>>>();
    compact_kernel<<<64, 256>>>(sigma, mu, w, erev, mask,   // 512 warps (256 rec + 256 sens)
                                ssigma, smu, sw, serev, smask);

    ltc_kernel<<<BATCH / BB, 512>>>(
        inputs, states, gleak, vleak, cm,
        input_w, input_b, output_w, output_b, out);
}